// round 16
// baseline (speedup 1.0000x reference)
#include <cuda_runtime.h>
#include <cuda_fp16.h>
#include <cstdint>

// Problem constants
#define Bsz 512
#define Hd  512
#define Km  6
#define Tt  60
#define OUTd 2
#define H2  1024
#define TO  120
#define ROWS_PER_MODE (Bsz*Tt)       // 30720
#define NROWS (Km*Bsz*Tt)            // 184320
#define PRED_ELEMS (Bsz*Km*Tt*OUTd)  // 368640

// refine GEMM tiling (R12 design: 2 CTAs/SM, 4-stage ring)
#define CH 32
#define NCHUNK (Hd/CH)               // 16
#define ROWB 80
#define PLANE (128*ROWB)
#define STAGE (2*PLANE)
#define NSTAGE 4
#define SMEM_DYN (NSTAGE*STAGE)      // 81920 B

// ---------------- scratch (device globals) ------------------------------------
#define OFF_WVO    0
#define OFF_TMP1   (OFF_WVO  + Hd*Hd)
#define OFF_CTX    (OFF_TMP1 + Bsz*Hd)
#define OFF_ATTN   (OFF_CTX  + Bsz*Hd)
#define OFF_COARSE (OFF_ATTN + Bsz*Hd)
#define OFF_C1     (OFF_COARSE + Bsz*Km*TO)
#define ACC_TOTAL  (OFF_C1   + Bsz*Km*64)
__device__ float g_accbuf[ACC_TOTAL];

__device__ float g_h[Bsz*Km*H2];
__device__ float g_bvo[Hd];
__device__ float g_zero512[Hd];
__device__ __half g_xh[(long long)NROWS*Hd];
__device__ __half g_w16[(long long)Km*Hd*Hd];

__device__ __forceinline__ float gelu_exact(float x){
    return 0.5f * x * (1.0f + erff(x * 0.7071067811865476f));
}

#define ACT_NONE 0
#define ACT_GELU 1
#define ACT_RELU 2

#define AM_PLAIN  0
#define AM_CONCAT 1
#define AM_CTXQ   2
#define AM_CONF   3
#define AM_GELU   4

// ---------------- PTX helpers ---------------------------------------------------
__device__ __forceinline__ uint32_t smem_to_u32(const void* p) {
    uint32_t a;
    asm("{ .reg .u64 t; cvta.to.shared.u64 t, %1; cvt.u32.u64 %0, t; }" : "=r"(a) : "l"(p));
    return a;
}
#define CP_ASYNC16(dst, src) \
    asm volatile("cp.async.cg.shared.global [%0], [%1], 16;" :: "r"(dst), "l"(src))
#define CP_COMMIT() asm volatile("cp.async.commit_group;" ::: "memory")
#define CP_WAITN(n) asm volatile("cp.async.wait_group %0;" :: "n"(n) : "memory")

#define LDMX4(R0,R1,R2,R3,addr) \
    asm volatile("ldmatrix.sync.aligned.m8n8.x4.shared.b16 {%0,%1,%2,%3}, [%4];" \
        : "=r"(R0),"=r"(R1),"=r"(R2),"=r"(R3) : "r"(addr))

__device__ __forceinline__ void mma16816(float* c, const uint32_t* a, uint32_t b0, uint32_t b1){
    asm volatile(
        "mma.sync.aligned.m16n8k16.row.col.f32.f16.f16.f32 "
        "{%0,%1,%2,%3}, {%4,%5,%6,%7}, {%8,%9}, {%0,%1,%2,%3};"
        : "+f"(c[0]), "+f"(c[1]), "+f"(c[2]), "+f"(c[3])
        : "r"(a[0]), "r"(a[1]), "r"(a[2]), "r"(a[3]), "r"(b0), "r"(b1));
}

// ---------------- shared A-loader for FFMA GEMMs --------------------------------
template<int AMODE>
__device__ __forceinline__ float4 loadA4g(const float* A, const float* A1, const float* A2,
                                          long long sAb, int lda, int bz, int m, int kk)
{
    if (AMODE == AM_PLAIN)
        return *reinterpret_cast<const float4*>(&A[bz*sAb + (long long)m*lda + kk]);
    if (AMODE == AM_CONCAT) {
        const float* p = (kk < 512) ? A : (kk < 1024) ? A1 : A2;
        return *reinterpret_cast<const float4*>(&p[(long long)m*512 + (kk & 511)]);
    }
    if (AMODE == AM_CTXQ) {
        float4 u = *reinterpret_cast<const float4*>(&A [(long long)m*512 + kk]);
        float4 v = *reinterpret_cast<const float4*>(&A1[(long long)bz*512 + kk]);
        return make_float4(u.x+v.x, u.y+v.y, u.z+v.z, u.w+v.w);
    }
    if (AMODE == AM_CONF) {
        int b = m / Km, km = m - b * Km;
        float4 u = *reinterpret_cast<const float4*>(&A [(long long)b*512 + kk]);
        float4 v = *reinterpret_cast<const float4*>(&A1[(long long)km*512 + kk]);
        return make_float4(u.x+v.x, u.y+v.y, u.z+v.z, u.w+v.w);
    }
    float4 u = *reinterpret_cast<const float4*>(&A[bz*sAb + (long long)m*lda + kk]);
    return make_float4(gelu_exact(u.x), gelu_exact(u.y), gelu_exact(u.z), gelu_exact(u.w));
}

// ---------------- FFMA SGEMM 64x64x16, register-prefetch double buffer ----------
template<int ACT, int AMODE>
__global__ __launch_bounds__(256)
void sgemm64(const float* __restrict__ A, const float* __restrict__ A1,
             const float* __restrict__ A2,
             long long sAb, int lda,
             const float* __restrict__ Bm, long long sBb, int ldb,
             const float* __restrict__ bias, long long sbias,
             float* __restrict__ C, long long sCb, int ldc,
             int M, int N, int Kd)
{
    constexpr int BM=64, BN=64, BK=16;
    __shared__ float As[BK][BM];
    __shared__ float Bs[BK][BN];
    const int bz = blockIdx.z;
    Bm += (long long)bz * sBb;
    C  += (long long)bz * sCb;
    const float* bptr = bias + (long long)bz * sbias;

    const int m0 = blockIdx.y * BM;
    const int n0 = blockIdx.x * BN;
    const int tid = threadIdx.x;
    const int trow = tid >> 4, tcol = tid & 15;
    const int a_r = tid >> 2, a_c = (tid & 3) * 4;
    const int b_r = tid >> 4, b_c = (tid & 15) * 4;

    auto loadB4 = [&](int kk, int n)->float4 {
        if (n + 3 < N)
            return *reinterpret_cast<const float4*>(&Bm[(long long)kk*ldb + n]);
        float4 r;
        r.x = (n+0 < N) ? Bm[(long long)kk*ldb + n+0] : 0.f;
        r.y = (n+1 < N) ? Bm[(long long)kk*ldb + n+1] : 0.f;
        r.z = (n+2 < N) ? Bm[(long long)kk*ldb + n+2] : 0.f;
        r.w = (n+3 < N) ? Bm[(long long)kk*ldb + n+3] : 0.f;
        return r;
    };

    float acc[4][4];
    #pragma unroll
    for (int i=0;i<4;i++)
        #pragma unroll
        for (int j=0;j<4;j++) acc[i][j]=0.f;

    float4 pa = loadA4g<AMODE>(A,A1,A2,sAb,lda,bz, m0 + a_r, a_c);
    float4 pb = loadB4(b_r, n0 + b_c);

    for (int k0 = 0; k0 < Kd; k0 += BK) {
        As[a_c+0][a_r]=pa.x; As[a_c+1][a_r]=pa.y; As[a_c+2][a_r]=pa.z; As[a_c+3][a_r]=pa.w;
        Bs[b_r][b_c+0]=pb.x; Bs[b_r][b_c+1]=pb.y; Bs[b_r][b_c+2]=pb.z; Bs[b_r][b_c+3]=pb.w;
        __syncthreads();
        if (k0 + BK < Kd) {
            pa = loadA4g<AMODE>(A,A1,A2,sAb,lda,bz, m0 + a_r, k0 + BK + a_c);
            pb = loadB4(k0 + BK + b_r, n0 + b_c);
        }
        #pragma unroll
        for (int kk=0; kk<BK; kk++){
            float4 a4 = *reinterpret_cast<const float4*>(&As[kk][trow*4]);
            float4 b4 = *reinterpret_cast<const float4*>(&Bs[kk][tcol*4]);
            float ar[4] = {a4.x,a4.y,a4.z,a4.w};
            float br[4] = {b4.x,b4.y,b4.z,b4.w};
            #pragma unroll
            for (int i=0;i<4;i++)
                #pragma unroll
                for (int j=0;j<4;j++)
                    acc[i][j] = fmaf(ar[i], br[j], acc[i][j]);
        }
        __syncthreads();
    }
    #pragma unroll
    for (int i=0;i<4;i++){
        int m = m0 + trow*4 + i;
        #pragma unroll
        for (int j=0;j<4;j++){
            int n = n0 + tcol*4 + j;
            if (n >= N) continue;
            float val = acc[i][j] + bptr[n];
            if (ACT==ACT_GELU) val = gelu_exact(val);
            else if (ACT==ACT_RELU) val = fmaxf(val, 0.f);
            C[(long long)m*ldc + n] = val;
        }
    }
}

// ---------------- batched split-K FFMA GEMM, atomic accumulation ----------------
template<int AMODE>
__global__ __launch_bounds__(256)
void sgemmskb(const float* __restrict__ A, const float* __restrict__ A1,
              const float* __restrict__ A2, long long sAb, int lda,
              const float* __restrict__ Bm, long long sBb, int ldb,
              const float* __restrict__ bias, long long sbias,
              float* __restrict__ C, long long sCb, int ldc,
              int M, int N, int kper, int ksplit)
{
    constexpr int BM=64, BN=64, BK=16;
    __shared__ float As[BK][BM];
    __shared__ float Bs[BK][BN];
    const int zz = blockIdx.z;
    const int kz = zz % ksplit;
    const int bz = zz / ksplit;
    const int kbase = kz * kper;
    Bm += (long long)bz * sBb;
    C  += (long long)bz * sCb;
    const float* bptr = bias + (long long)bz * sbias;

    const int m0 = blockIdx.y * BM;
    const int n0 = blockIdx.x * BN;
    const int tid = threadIdx.x;
    const int trow = tid >> 4, tcol = tid & 15;
    const int a_r = tid >> 2, a_c = (tid & 3) * 4;
    const int b_r = tid >> 4, b_c = (tid & 15) * 4;

    auto loadB4 = [&](int kk, int n)->float4 {
        if (n + 3 < N)
            return *reinterpret_cast<const float4*>(&Bm[(long long)kk*ldb + n]);
        float4 r;
        r.x = (n+0 < N) ? Bm[(long long)kk*ldb + n+0] : 0.f;
        r.y = (n+1 < N) ? Bm[(long long)kk*ldb + n+1] : 0.f;
        r.z = (n+2 < N) ? Bm[(long long)kk*ldb + n+2] : 0.f;
        r.w = (n+3 < N) ? Bm[(long long)kk*ldb + n+3] : 0.f;
        return r;
    };

    float acc[4][4];
    #pragma unroll
    for (int i=0;i<4;i++)
        #pragma unroll
        for (int j=0;j<4;j++) acc[i][j]=0.f;

    float4 pa = loadA4g<AMODE>(A,A1,A2,sAb,lda,bz, m0 + a_r, kbase + a_c);
    float4 pb = loadB4(kbase + b_r, n0 + b_c);

    for (int k0 = 0; k0 < kper; k0 += BK) {
        As[a_c+0][a_r]=pa.x; As[a_c+1][a_r]=pa.y; As[a_c+2][a_r]=pa.z; As[a_c+3][a_r]=pa.w;
        Bs[b_r][b_c+0]=pb.x; Bs[b_r][b_c+1]=pb.y; Bs[b_r][b_c+2]=pb.z; Bs[b_r][b_c+3]=pb.w;
        __syncthreads();
        if (k0 + BK < kper) {
            pa = loadA4g<AMODE>(A,A1,A2,sAb,lda,bz, m0 + a_r, kbase + k0 + BK + a_c);
            pb = loadB4(kbase + k0 + BK + b_r, n0 + b_c);
        }
        #pragma unroll
        for (int kk=0; kk<BK; kk++){
            float4 a4 = *reinterpret_cast<const float4*>(&As[kk][trow*4]);
            float4 b4 = *reinterpret_cast<const float4*>(&Bs[kk][tcol*4]);
            float ar[4] = {a4.x,a4.y,a4.z,a4.w};
            float br[4] = {b4.x,b4.y,b4.z,b4.w};
            #pragma unroll
            for (int i=0;i<4;i++)
                #pragma unroll
                for (int j=0;j<4;j++)
                    acc[i][j] = fmaf(ar[i], br[j], acc[i][j]);
        }
        __syncthreads();
    }
    #pragma unroll
    for (int i=0;i<4;i++){
        int m = m0 + trow*4 + i;
        #pragma unroll
        for (int j=0;j<4;j++){
            int n = n0 + tcol*4 + j;
            if (n >= N) continue;
            float val = acc[i][j] + ((kz == 0) ? bptr[n] : 0.f);
            atomicAdd(&C[(long long)m*ldc + n], val);
        }
    }
}

// ---------------- small prep kernels --------------------------------------------
__global__ void bvo_kernel(const float* __restrict__ bv, const float* __restrict__ Wo,
                           const float* __restrict__ bo, float* __restrict__ bvo)
{
    int n = blockIdx.x*blockDim.x + threadIdx.x;
    if (n >= Hd) return;
    float s = bo[n];
    for (int k = 0; k < Hd; k++) s = fmaf(bv[k], Wo[k*Hd + n], s);
    bvo[n] = s;
}

__global__ void prep_w_kernel(const float* __restrict__ Wr1, __half* __restrict__ W16)
{
    long long idx = (long long)blockIdx.x*blockDim.x + threadIdx.x;
    if (idx >= (long long)Km*Hd*Hd) return;
    int kk = idx & 511;
    int n  = (idx >> 9) & 511;
    int k  = idx >> 18;
    W16[idx] = __float2half_rn(Wr1[((long long)k*Hd + kk)*Hd + n]);
}

// out[pred region] = coarse + br2 (rewritten each replay; refine atomicAdds on top)
__global__ void init_out_kernel(const float* __restrict__ coarse,
                                const float* __restrict__ br2,
                                float* __restrict__ out)
{
    int idx = blockIdx.x*blockDim.x + threadIdx.x;
    if (idx >= PRED_ELEMS) return;
    int o = idx & 1;
    int k = ((idx >> 1) / Tt) % Km;
    out[idx] = coarse[idx] + br2[k*2+o];
}

// Fused traj+LN, warp-per-row (8 rows/block); lane handles 16 CONTIGUOUS h
// (vectorized float4 loads + uint4 stores). Two-pass centered stats.
__global__ __launch_bounds__(256)
void traj_ln_kernel(const float* __restrict__ coarse,
                    const float* __restrict__ attn,
                    const float* __restrict__ Wt,
                    const float* __restrict__ bt,
                    const float* __restrict__ ln_g,
                    const float* __restrict__ ln_b,
                    __half* __restrict__ XH)
{
    const int wid  = threadIdx.x >> 5;
    const int lane = threadIdx.x & 31;
    const int row  = blockIdx.x * 8 + wid;
    const int k    = row / ROWS_PER_MODE;
    const int rem  = row % ROWS_PER_MODE;
    const int b    = rem / Tt;
    const int t    = rem % Tt;
    const float2 cc = *reinterpret_cast<const float2*>(
        &coarse[((b*Km + k)*Tt + t)*OUTd]);
    const int h0 = lane * 16;

    float u[16];
    float s = 0.f;
    #pragma unroll
    for (int q4 = 0; q4 < 4; q4++){
        float4 w0 = *reinterpret_cast<const float4*>(&Wt[h0 + q4*4]);
        float4 w1 = *reinterpret_cast<const float4*>(&Wt[Hd + h0 + q4*4]);
        float4 b4 = *reinterpret_cast<const float4*>(&bt[h0 + q4*4]);
        float4 a4 = *reinterpret_cast<const float4*>(&attn[(long long)b*Hd + h0 + q4*4]);
        float pre0 = fmaf(cc.x, w0.x, fmaf(cc.y, w1.x, b4.x));
        float pre1 = fmaf(cc.x, w0.y, fmaf(cc.y, w1.y, b4.y));
        float pre2 = fmaf(cc.x, w0.z, fmaf(cc.y, w1.z, b4.z));
        float pre3 = fmaf(cc.x, w0.w, fmaf(cc.y, w1.w, b4.w));
        u[q4*4+0] = gelu_exact(pre0) + a4.x;
        u[q4*4+1] = gelu_exact(pre1) + a4.y;
        u[q4*4+2] = gelu_exact(pre2) + a4.z;
        u[q4*4+3] = gelu_exact(pre3) + a4.w;
        s += u[q4*4+0] + u[q4*4+1] + u[q4*4+2] + u[q4*4+3];
    }
    #pragma unroll
    for (int o=16;o>0;o>>=1) s += __shfl_xor_sync(0xffffffffu, s, o);
    const float mean = s * (1.f/512.f);

    float vs = 0.f;
    #pragma unroll
    for (int q=0;q<16;q++){ float d = u[q] - mean; vs = fmaf(d, d, vs); }
    #pragma unroll
    for (int o=16;o>0;o>>=1) vs += __shfl_xor_sync(0xffffffffu, vs, o);
    const float rstd = rsqrtf(vs * (1.f/512.f) + 1e-5f);

    __half2 hv[8];
    #pragma unroll
    for (int q4 = 0; q4 < 4; q4++){
        float4 g4 = *reinterpret_cast<const float4*>(&ln_g[h0 + q4*4]);
        float4 bb = *reinterpret_cast<const float4*>(&ln_b[h0 + q4*4]);
        float x0 = (u[q4*4+0] - mean) * rstd * g4.x + bb.x;
        float x1 = (u[q4*4+1] - mean) * rstd * g4.y + bb.y;
        float x2 = (u[q4*4+2] - mean) * rstd * g4.z + bb.z;
        float x3 = (u[q4*4+3] - mean) * rstd * g4.w + bb.w;
        hv[q4*2+0] = __floats2half2_rn(x0, x1);
        hv[q4*2+1] = __floats2half2_rn(x2, x3);
    }
    long long rbase = (long long)row * Hd + h0;
    *reinterpret_cast<uint4*>(&XH[rbase])     = *reinterpret_cast<uint4*>(&hv[0]);
    *reinterpret_cast<uint4*>(&XH[rbase + 8]) = *reinterpret_cast<uint4*>(&hv[4]);
}

// ---------------- refine GEMM: fp32-acc HMMA, ldmatrix, 4-stage cp.async --------
// grid (nt=4, mtile=240, mode=6), 256 threads = 8 warps (4 m x 2 n), warp 32x64.
// Epilogue atomicAdds GELU(pre+br1)@Wr2 partials directly into out (init_out first).
__global__ __launch_bounds__(256,2)
void refine_mma_kernel(const __half* __restrict__ XH,
                       const __half* __restrict__ W16,
                       const float* __restrict__ br1,
                       const float* __restrict__ Wr2,
                       float* __restrict__ out)
{
    extern __shared__ char smem[];
    const uint32_t sbase = smem_to_u32(smem);
    const int tid  = threadIdx.x;
    const int wid  = tid >> 5;
    const int lane = tid & 31;
    const int wm   = wid & 3;
    const int wn   = wid >> 2;
    const int nt   = blockIdx.x;
    const int m0   = blockIdx.y * 128;
    const int mode = blockIdx.z;

    const __half* xh = XH  + ((long long)mode * ROWS_PER_MODE + m0) * Hd;
    const __half* wv = W16 + ((long long)mode * Hd + nt * 128) * Hd;

    float acc[2][8][4];
    #pragma unroll
    for (int i=0;i<2;i++)
        #pragma unroll
        for (int j=0;j<8;j++)
            #pragma unroll
            for (int q=0;q<4;q++) acc[i][j][q]=0.f;

    const int lr = tid >> 1;
    const int lh = (tid & 1) * 32;
    auto load_chunk = [&](int c, int stage){
        uint32_t sb = sbase + stage * STAGE;
        const __half* srcs[2] = {xh, wv};
        #pragma unroll
        for (int p = 0; p < 2; p++) {
            uint32_t dst = sb + p*PLANE + lr*ROWB + lh;
            const char* g = (const char*)srcs[p] + ((long long)lr*Hd + c*CH)*2 + lh;
            CP_ASYNC16(dst, g);
            CP_ASYNC16(dst + 16, g + 16);
        }
    };

    load_chunk(0, 0); CP_COMMIT();
    load_chunk(1, 1); CP_COMMIT();
    load_chunk(2, 2); CP_COMMIT();

    const int l16 = lane & 15;
    const int lhf = (lane >> 4) * 16;

    #pragma unroll 1
    for (int c = 0; c < NCHUNK; c++) {
        if (c < NCHUNK-2)       CP_WAITN(2);
        else if (c == NCHUNK-2) CP_WAITN(1);
        else                    CP_WAITN(0);
        __syncthreads();
        if (c + 3 < NCHUNK) { load_chunk(c + 3, (c + 3) & (NSTAGE-1)); CP_COMMIT(); }

        const uint32_t sb = sbase + (c & (NSTAGE-1)) * STAGE;
        #pragma unroll
        for (int ks = 0; ks < 2; ks++) {
            uint32_t ah[2][4];
            #pragma unroll
            for (int i=0;i<2;i++){
                uint32_t a = sb + (wm*32 + i*16 + l16)*ROWB + ks*32 + lhf;
                LDMX4(ah[i][0], ah[i][1], ah[i][2], ah[i][3], a);
            }
            #pragma unroll
            for (int jp=0;jp<4;jp++){
                uint32_t q0,q1,q2,q3;
                uint32_t b = sb + PLANE + (wn*64 + jp*16 + l16)*ROWB + ks*32 + lhf;
                LDMX4(q0,q1,q2,q3, b);
                #pragma unroll
                for (int i=0;i<2;i++){
                    mma16816(acc[i][2*jp+0], ah[i], q0, q2);
                    mma16816(acc[i][2*jp+1], ah[i], q1, q3);
                }
            }
        }
        __syncthreads();
    }

    // epilogue: GELU(pre + br1) dot Wr2
    const float* br1m = br1 + mode * Hd;
    const float* wr2m = Wr2 + mode * Hd * OUTd;
    const int nloc0 = nt*128 + wn*64;

    float p0[2][2], p1[2][2];
    #pragma unroll
    for (int i=0;i<2;i++)
        #pragma unroll
        for (int h2=0;h2<2;h2++){ p0[i][h2]=0.f; p1[i][h2]=0.f; }

    #pragma unroll
    for (int j=0;j<8;j++){
        #pragma unroll
        for (int nn=0;nn<2;nn++){
            const int n = nloc0 + j*8 + (lane&3)*2 + nn;
            const float bv = br1m[n];
            const float w0 = wr2m[n*2+0];
            const float w1 = wr2m[n*2+1];
            #pragma unroll
            for (int i=0;i<2;i++){
                #pragma unroll
                for (int h2=0;h2<2;h2++){
                    float r = gelu_exact(acc[i][j][h2*2+nn] + bv);
                    p0[i][h2] = fmaf(r, w0, p0[i][h2]);
                    p1[i][h2] = fmaf(r, w1, p1[i][h2]);
                }
            }
        }
    }
    #pragma unroll
    for (int i=0;i<2;i++)
        #pragma unroll
        for (int h2=0;h2<2;h2++){
            #pragma unroll
            for (int o=1;o<4;o<<=1){
                p0[i][h2] += __shfl_xor_sync(0xffffffffu, p0[i][h2], o);
                p1[i][h2] += __shfl_xor_sync(0xffffffffu, p1[i][h2], o);
            }
        }

    __syncthreads();
    float* red0 = reinterpret_cast<float*>(smem);
    float* red1 = red0 + 128;
    if (wn == 0 && (lane & 3) == 0){
        #pragma unroll
        for (int i=0;i<2;i++)
            #pragma unroll
            for (int h2=0;h2<2;h2++){
                int rl = wm*32 + i*16 + h2*8 + (lane>>2);
                red0[rl] = p0[i][h2];
                red1[rl] = p1[i][h2];
            }
    }
    __syncthreads();
    if (wn == 1 && (lane & 3) == 0){
        #pragma unroll
        for (int i=0;i<2;i++)
            #pragma unroll
            for (int h2=0;h2<2;h2++){
                int rl = wm*32 + i*16 + h2*8 + (lane>>2);
                int rem = m0 + rl;
                int b = rem / Tt, t = rem - b * Tt;
                long long oidx = (((long long)b*Km + mode)*Tt + t)*OUTd;
                atomicAdd(&out[oidx + 0], p0[i][h2] + red0[rl]);
                atomicAdd(&out[oidx + 1], p1[i][h2] + red1[rl]);
            }
    }
}

// conf head epilogue + softmax (c1 holds raw pre-activation; ReLU applied here)
__global__ __launch_bounds__(192)
void conf_softmax_kernel(const float* __restrict__ C1,
                         const float* __restrict__ Wf2,
                         const float* __restrict__ bf2,
                         float* __restrict__ out)
{
    int b = blockIdx.x;
    int tid = threadIdx.x;
    int k = tid >> 5, lane = tid & 31;
    __shared__ float cf[Km];
    const float* row = C1 + (b*Km + k)*64;
    float s = fmaxf(row[lane],      0.f) * Wf2[lane]
            + fmaxf(row[32 + lane], 0.f) * Wf2[32 + lane];
    #pragma unroll
    for (int o=16;o>0;o>>=1) s += __shfl_xor_sync(0xffffffffu, s, o);
    if (lane == 0) cf[k] = s + bf2[0];
    __syncthreads();
    if (tid < Km){
        float m = cf[0];
        #pragma unroll
        for (int i=1;i<Km;i++) m = fmaxf(m, cf[i]);
        float denom = 0.f;
        #pragma unroll
        for (int i=0;i<Km;i++) denom += expf(cf[i]-m);
        out[PRED_ELEMS + b*Km + tid] = expf(cf[tid]-m)/denom;
    }
}

// ------------------------------- launch ------------------------------------------
extern "C" void kernel_launch(void* const* d_in, const int* in_sizes, int n_in,
                              void* d_out, int out_size)
{
    const float* interaction = (const float*)d_in[0];
    const float* cooperative = (const float*)d_in[1];
    const float* map_ctx     = (const float*)d_in[2];
    const float* mode_q      = (const float*)d_in[3];
    const float* Wc1 = (const float*)d_in[4];
    const float* bc1 = (const float*)d_in[5];
    const float* Wc2 = (const float*)d_in[6];
    const float* bc2 = (const float*)d_in[7];
    const float* Wk1 = (const float*)d_in[8];
    const float* bk1 = (const float*)d_in[9];
    const float* Wk2 = (const float*)d_in[10];
    const float* bk2 = (const float*)d_in[11];
    const float* Wt  = (const float*)d_in[12];
    const float* bt  = (const float*)d_in[13];
    const float* Wv  = (const float*)d_in[18];
    const float* bv  = (const float*)d_in[19];
    const float* Wo  = (const float*)d_in[20];
    const float* bo  = (const float*)d_in[21];
    const float* lng = (const float*)d_in[22];
    const float* lnb = (const float*)d_in[23];
    const float* Wr1 = (const float*)d_in[24];
    const float* br1 = (const float*)d_in[25];
    const float* Wr2 = (const float*)d_in[26];
    const float* br2 = (const float*)d_in[27];
    const float* Wf1 = (const float*)d_in[28];
    const float* bf1 = (const float*)d_in[29];
    const float* Wf2 = (const float*)d_in[30];
    const float* bf2 = (const float*)d_in[31];
    float* out = (float*)d_out;

    float *accbuf, *hbuf, *bvo, *zero;
    __half *xh, *w16;
    cudaGetSymbolAddress((void**)&accbuf, g_accbuf);
    cudaGetSymbolAddress((void**)&hbuf,   g_h);
    cudaGetSymbolAddress((void**)&bvo,    g_bvo);
    cudaGetSymbolAddress((void**)&zero,   g_zero512);
    cudaGetSymbolAddress((void**)&xh,     g_xh);
    cudaGetSymbolAddress((void**)&w16,    g_w16);

    float* wvo    = accbuf + OFF_WVO;
    float* tmp1   = accbuf + OFF_TMP1;
    float* ctx    = accbuf + OFF_CTX;
    float* attn   = accbuf + OFF_ATTN;
    float* coarse = accbuf + OFF_COARSE;
    float* c1     = accbuf + OFF_C1;

    static cudaStream_t s1 = nullptr, s2 = nullptr;
    static cudaEvent_t evRoot, evCtx, evAttn, evPrep, evConf;
    if (!s1) {
        cudaStreamCreateWithFlags(&s1, cudaStreamNonBlocking);
        cudaStreamCreateWithFlags(&s2, cudaStreamNonBlocking);
        cudaEventCreateWithFlags(&evRoot, cudaEventDisableTiming);
        cudaEventCreateWithFlags(&evCtx,  cudaEventDisableTiming);
        cudaEventCreateWithFlags(&evAttn, cudaEventDisableTiming);
        cudaEventCreateWithFlags(&evPrep, cudaEventDisableTiming);
        cudaEventCreateWithFlags(&evConf, cudaEventDisableTiming);
        cudaFuncSetAttribute(refine_mma_kernel,
                             cudaFuncAttributeMaxDynamicSharedMemorySize, SMEM_DYN);
    }

    // ---- fork ----
    cudaEventRecord(evRoot, 0);
    cudaStreamWaitEvent(s1, evRoot, 0);
    cudaStreamWaitEvent(s2, evRoot, 0);

    // s1: refine weight prep (independent)
    prep_w_kernel<<<(Km*Hd*Hd + 255)/256, 256, 0, s1>>>(Wr1, w16);
    cudaEventRecord(evPrep, s1);

    // s2: wvo = Wv@Wo (+ its memset) and bvo (independent of data chain)
    cudaMemsetAsync(wvo, 0, (size_t)Hd*Hd*sizeof(float), s2);
    sgemmskb<AM_PLAIN><<<dim3(8,8,8),256,0,s2>>>(Wv,nullptr,nullptr,0,Hd, Wo,0,Hd, zero,0,
                                                 wvo,0,Hd, Hd,Hd, Hd/8, 8);
    bvo_kernel<<<2,256,0,s2>>>(bv, Wo, bo, bvo);

    // s0: main chain — memset, then context_proj
    cudaMemsetAsync(tmp1, 0, (size_t)(ACC_TOTAL - OFF_TMP1)*sizeof(float));
    sgemmskb<AM_CONCAT><<<dim3(8,8,8),256>>>(interaction,cooperative,map_ctx,0,0,
                                             Wc1,0,Hd, bc1,0, tmp1,0,Hd, Bsz,Hd, (3*Hd)/8, 8);
    sgemmskb<AM_GELU><<<dim3(8,8,8),256>>>(tmp1,nullptr,nullptr,0,Hd,
                                           Wc2,0,Hd, bc2,0, ctx,0,Hd, Bsz,Hd, Hd/8, 8);
    cudaEventRecord(evCtx, 0);

    // s2: attn = ctx @ wvo + bvo
    cudaStreamWaitEvent(s2, evCtx, 0);
    sgemmskb<AM_PLAIN><<<dim3(8,8,8),256,0,s2>>>(ctx,nullptr,nullptr,0,Hd,
                                                 wvo,0,Hd, bvo,0, attn,0,Hd, Bsz,Hd, Hd/8, 8);
    cudaEventRecord(evAttn, s2);

    // s1: confidence branch
    cudaStreamWaitEvent(s1, evCtx, 0);
    sgemmskb<AM_CONF><<<dim3(1,48,4),256,0,s1>>>(ctx,mode_q,nullptr,0,0,
                                                 Wf1,0,64, bf1,0, c1,0,64, Bsz*Km,64, Hd/4, 4);
    conf_softmax_kernel<<<Bsz,192,0,s1>>>(c1, Wf2, bf2, out);
    cudaEventRecord(evConf, s1);

    // s0: coarse heads (R12 exact config: sgemm64 for Wk1, split-K x4 for Wk2)
    sgemm64<ACT_NONE,AM_CTXQ><<<dim3(16,8,Km),256>>>(ctx,mode_q,nullptr,0,0,
                                                     Wk1,(long long)Hd*H2,H2,
                                                     bk1,H2, hbuf,H2,Km*H2, Bsz,H2,Hd);
    sgemmskb<AM_GELU><<<dim3(2,8,Km*4),256>>>(hbuf,nullptr,nullptr,H2,Km*H2,
                                              Wk2,(long long)H2*TO,TO,
                                              bk2,TO, coarse,TO,Km*TO, Bsz,TO, H2/4, 4);

    // s0: init out with coarse + br2 (refine atomicAdds partials on top)
    init_out_kernel<<<(PRED_ELEMS + 255)/256, 256>>>(coarse, br2, out);

    // s0: traj+LN (needs coarse on s0 + attn from s2)
    cudaStreamWaitEvent(0, evAttn, 0);
    traj_ln_kernel<<<NROWS/8,256>>>(coarse, attn, Wt, bt, lng, lnb, xh);

    // s0: refine GEMM (needs xh + w16 from s1's prep); writes predictions directly
    cudaStreamWaitEvent(0, evPrep, 0);
    refine_mma_kernel<<<dim3(4,240,Km),256, SMEM_DYN>>>(xh, w16, br1, Wr2, out);

    // join conf branch
    cudaStreamWaitEvent(0, evConf, 0);
}

// round 17
// speedup vs baseline: 1.1526x; 1.1526x over previous
#include <cuda_runtime.h>
#include <cuda_fp16.h>
#include <cstdint>

// Problem constants
#define Bsz 512
#define Hd  512
#define Km  6
#define Tt  60
#define OUTd 2
#define H2  1024
#define TO  120
#define ROWS_PER_MODE (Bsz*Tt)       // 30720
#define NROWS (Km*Bsz*Tt)            // 184320
#define PRED_ELEMS (Bsz*Km*Tt*OUTd)  // 368640

// refine GEMM tiling
#define CH 32
#define NCHUNK (Hd/CH)               // 16
#define ROWB 80
#define PLANE (128*ROWB)
#define STAGE (2*PLANE)
#define NSTAGE 4
#define SMEM_DYN (NSTAGE*STAGE)      // 81920 B

// ---------------- scratch (device globals) ------------------------------------
#define OFF_WVO    0
#define OFF_TMP1   (OFF_WVO  + Hd*Hd)
#define OFF_CTX    (OFF_TMP1 + Bsz*Hd)
#define OFF_ATTN   (OFF_CTX  + Bsz*Hd)
#define OFF_COARSE (OFF_ATTN + Bsz*Hd)
#define OFF_C1     (OFF_COARSE + Bsz*Km*TO)
#define ACC_TOTAL  (OFF_C1   + Bsz*Km*64)
__device__ float g_accbuf[ACC_TOTAL];

__device__ float g_h[Bsz*Km*H2];
__device__ float g_bvo[Hd];
__device__ float g_zero512[Hd];
__device__ __half g_xh[(long long)NROWS*Hd];
__device__ __half g_w16[(long long)Km*Hd*Hd];
__device__ float g_part[4LL*NROWS*OUTd];

__device__ __forceinline__ float gelu_exact(float x){
    return 0.5f * x * (1.0f + erff(x * 0.7071067811865476f));
}

#define ACT_NONE 0
#define ACT_GELU 1
#define ACT_RELU 2

#define AM_PLAIN  0
#define AM_CONCAT 1
#define AM_CTXQ   2
#define AM_CONF   3
#define AM_GELU   4

// ---------------- PTX helpers ---------------------------------------------------
__device__ __forceinline__ uint32_t smem_to_u32(const void* p) {
    uint32_t a;
    asm("{ .reg .u64 t; cvta.to.shared.u64 t, %1; cvt.u32.u64 %0, t; }" : "=r"(a) : "l"(p));
    return a;
}
#define CP_ASYNC16(dst, src) \
    asm volatile("cp.async.cg.shared.global [%0], [%1], 16;" :: "r"(dst), "l"(src))
#define CP_COMMIT() asm volatile("cp.async.commit_group;" ::: "memory")
#define CP_WAITN(n) asm volatile("cp.async.wait_group %0;" :: "n"(n) : "memory")

#define LDMX4(R0,R1,R2,R3,addr) \
    asm volatile("ldmatrix.sync.aligned.m8n8.x4.shared.b16 {%0,%1,%2,%3}, [%4];" \
        : "=r"(R0),"=r"(R1),"=r"(R2),"=r"(R3) : "r"(addr))

__device__ __forceinline__ void mma16816(float* c, const uint32_t* a, uint32_t b0, uint32_t b1){
    asm volatile(
        "mma.sync.aligned.m16n8k16.row.col.f32.f16.f16.f32 "
        "{%0,%1,%2,%3}, {%4,%5,%6,%7}, {%8,%9}, {%0,%1,%2,%3};"
        : "+f"(c[0]), "+f"(c[1]), "+f"(c[2]), "+f"(c[3])
        : "r"(a[0]), "r"(a[1]), "r"(a[2]), "r"(a[3]), "r"(b0), "r"(b1));
}

// ---------------- shared A-loader for FFMA GEMMs --------------------------------
template<int AMODE>
__device__ __forceinline__ float4 loadA4g(const float* A, const float* A1, const float* A2,
                                          long long sAb, int lda, int bz, int m, int kk)
{
    if (AMODE == AM_PLAIN)
        return *reinterpret_cast<const float4*>(&A[bz*sAb + (long long)m*lda + kk]);
    if (AMODE == AM_CONCAT) {
        const float* p = (kk < 512) ? A : (kk < 1024) ? A1 : A2;
        return *reinterpret_cast<const float4*>(&p[(long long)m*512 + (kk & 511)]);
    }
    if (AMODE == AM_CTXQ) {
        float4 u = *reinterpret_cast<const float4*>(&A [(long long)m*512 + kk]);
        float4 v = *reinterpret_cast<const float4*>(&A1[(long long)bz*512 + kk]);
        return make_float4(u.x+v.x, u.y+v.y, u.z+v.z, u.w+v.w);
    }
    if (AMODE == AM_CONF) {
        int b = m / Km, km = m - b * Km;
        float4 u = *reinterpret_cast<const float4*>(&A [(long long)b*512 + kk]);
        float4 v = *reinterpret_cast<const float4*>(&A1[(long long)km*512 + kk]);
        return make_float4(u.x+v.x, u.y+v.y, u.z+v.z, u.w+v.w);
    }
    float4 u = *reinterpret_cast<const float4*>(&A[bz*sAb + (long long)m*lda + kk]);
    return make_float4(gelu_exact(u.x), gelu_exact(u.y), gelu_exact(u.z), gelu_exact(u.w));
}

// ---------------- FFMA SGEMM 64x64x16, register-prefetch double buffer ----------
template<int ACT, int AMODE>
__global__ __launch_bounds__(256)
void sgemm64(const float* __restrict__ A, const float* __restrict__ A1,
             const float* __restrict__ A2,
             long long sAb, int lda,
             const float* __restrict__ Bm, long long sBb, int ldb,
             const float* __restrict__ bias, long long sbias,
             float* __restrict__ C, long long sCb, int ldc,
             int M, int N, int Kd)
{
    constexpr int BM=64, BN=64, BK=16;
    __shared__ float As[BK][BM];
    __shared__ float Bs[BK][BN];
    const int bz = blockIdx.z;
    Bm += (long long)bz * sBb;
    C  += (long long)bz * sCb;
    const float* bptr = bias + (long long)bz * sbias;

    const int m0 = blockIdx.y * BM;
    const int n0 = blockIdx.x * BN;
    const int tid = threadIdx.x;
    const int trow = tid >> 4, tcol = tid & 15;
    const int a_r = tid >> 2, a_c = (tid & 3) * 4;
    const int b_r = tid >> 4, b_c = (tid & 15) * 4;

    auto loadB4 = [&](int kk, int n)->float4 {
        if (n + 3 < N)
            return *reinterpret_cast<const float4*>(&Bm[(long long)kk*ldb + n]);
        float4 r;
        r.x = (n+0 < N) ? Bm[(long long)kk*ldb + n+0] : 0.f;
        r.y = (n+1 < N) ? Bm[(long long)kk*ldb + n+1] : 0.f;
        r.z = (n+2 < N) ? Bm[(long long)kk*ldb + n+2] : 0.f;
        r.w = (n+3 < N) ? Bm[(long long)kk*ldb + n+3] : 0.f;
        return r;
    };

    float acc[4][4];
    #pragma unroll
    for (int i=0;i<4;i++)
        #pragma unroll
        for (int j=0;j<4;j++) acc[i][j]=0.f;

    float4 pa = loadA4g<AMODE>(A,A1,A2,sAb,lda,bz, m0 + a_r, a_c);
    float4 pb = loadB4(b_r, n0 + b_c);

    for (int k0 = 0; k0 < Kd; k0 += BK) {
        As[a_c+0][a_r]=pa.x; As[a_c+1][a_r]=pa.y; As[a_c+2][a_r]=pa.z; As[a_c+3][a_r]=pa.w;
        Bs[b_r][b_c+0]=pb.x; Bs[b_r][b_c+1]=pb.y; Bs[b_r][b_c+2]=pb.z; Bs[b_r][b_c+3]=pb.w;
        __syncthreads();
        if (k0 + BK < Kd) {
            pa = loadA4g<AMODE>(A,A1,A2,sAb,lda,bz, m0 + a_r, k0 + BK + a_c);
            pb = loadB4(k0 + BK + b_r, n0 + b_c);
        }
        #pragma unroll
        for (int kk=0; kk<BK; kk++){
            float4 a4 = *reinterpret_cast<const float4*>(&As[kk][trow*4]);
            float4 b4 = *reinterpret_cast<const float4*>(&Bs[kk][tcol*4]);
            float ar[4] = {a4.x,a4.y,a4.z,a4.w};
            float br[4] = {b4.x,b4.y,b4.z,b4.w};
            #pragma unroll
            for (int i=0;i<4;i++)
                #pragma unroll
                for (int j=0;j<4;j++)
                    acc[i][j] = fmaf(ar[i], br[j], acc[i][j]);
        }
        __syncthreads();
    }
    #pragma unroll
    for (int i=0;i<4;i++){
        int m = m0 + trow*4 + i;
        #pragma unroll
        for (int j=0;j<4;j++){
            int n = n0 + tcol*4 + j;
            if (n >= N) continue;
            float val = acc[i][j] + bptr[n];
            if (ACT==ACT_GELU) val = gelu_exact(val);
            else if (ACT==ACT_RELU) val = fmaxf(val, 0.f);
            C[(long long)m*ldc + n] = val;
        }
    }
}

// ---------------- batched split-K FFMA GEMM, atomic accumulation ----------------
template<int AMODE>
__global__ __launch_bounds__(256)
void sgemmskb(const float* __restrict__ A, const float* __restrict__ A1,
              const float* __restrict__ A2, long long sAb, int lda,
              const float* __restrict__ Bm, long long sBb, int ldb,
              const float* __restrict__ bias, long long sbias,
              float* __restrict__ C, long long sCb, int ldc,
              int M, int N, int kper, int ksplit)
{
    constexpr int BM=64, BN=64, BK=16;
    __shared__ float As[BK][BM];
    __shared__ float Bs[BK][BN];
    const int zz = blockIdx.z;
    const int kz = zz % ksplit;
    const int bz = zz / ksplit;
    const int kbase = kz * kper;
    Bm += (long long)bz * sBb;
    C  += (long long)bz * sCb;
    const float* bptr = bias + (long long)bz * sbias;

    const int m0 = blockIdx.y * BM;
    const int n0 = blockIdx.x * BN;
    const int tid = threadIdx.x;
    const int trow = tid >> 4, tcol = tid & 15;
    const int a_r = tid >> 2, a_c = (tid & 3) * 4;
    const int b_r = tid >> 4, b_c = (tid & 15) * 4;

    auto loadB4 = [&](int kk, int n)->float4 {
        if (n + 3 < N)
            return *reinterpret_cast<const float4*>(&Bm[(long long)kk*ldb + n]);
        float4 r;
        r.x = (n+0 < N) ? Bm[(long long)kk*ldb + n+0] : 0.f;
        r.y = (n+1 < N) ? Bm[(long long)kk*ldb + n+1] : 0.f;
        r.z = (n+2 < N) ? Bm[(long long)kk*ldb + n+2] : 0.f;
        r.w = (n+3 < N) ? Bm[(long long)kk*ldb + n+3] : 0.f;
        return r;
    };

    float acc[4][4];
    #pragma unroll
    for (int i=0;i<4;i++)
        #pragma unroll
        for (int j=0;j<4;j++) acc[i][j]=0.f;

    float4 pa = loadA4g<AMODE>(A,A1,A2,sAb,lda,bz, m0 + a_r, kbase + a_c);
    float4 pb = loadB4(kbase + b_r, n0 + b_c);

    for (int k0 = 0; k0 < kper; k0 += BK) {
        As[a_c+0][a_r]=pa.x; As[a_c+1][a_r]=pa.y; As[a_c+2][a_r]=pa.z; As[a_c+3][a_r]=pa.w;
        Bs[b_r][b_c+0]=pb.x; Bs[b_r][b_c+1]=pb.y; Bs[b_r][b_c+2]=pb.z; Bs[b_r][b_c+3]=pb.w;
        __syncthreads();
        if (k0 + BK < kper) {
            pa = loadA4g<AMODE>(A,A1,A2,sAb,lda,bz, m0 + a_r, kbase + k0 + BK + a_c);
            pb = loadB4(kbase + k0 + BK + b_r, n0 + b_c);
        }
        #pragma unroll
        for (int kk=0; kk<BK; kk++){
            float4 a4 = *reinterpret_cast<const float4*>(&As[kk][trow*4]);
            float4 b4 = *reinterpret_cast<const float4*>(&Bs[kk][tcol*4]);
            float ar[4] = {a4.x,a4.y,a4.z,a4.w};
            float br[4] = {b4.x,b4.y,b4.z,b4.w};
            #pragma unroll
            for (int i=0;i<4;i++)
                #pragma unroll
                for (int j=0;j<4;j++)
                    acc[i][j] = fmaf(ar[i], br[j], acc[i][j]);
        }
        __syncthreads();
    }
    #pragma unroll
    for (int i=0;i<4;i++){
        int m = m0 + trow*4 + i;
        #pragma unroll
        for (int j=0;j<4;j++){
            int n = n0 + tcol*4 + j;
            if (n >= N) continue;
            float val = acc[i][j] + ((kz == 0) ? bptr[n] : 0.f);
            atomicAdd(&C[(long long)m*ldc + n], val);
        }
    }
}

// ---------------- small prep kernels --------------------------------------------
__global__ void bvo_kernel(const float* __restrict__ bv, const float* __restrict__ Wo,
                           const float* __restrict__ bo, float* __restrict__ bvo)
{
    int n = blockIdx.x*blockDim.x + threadIdx.x;
    if (n >= Hd) return;
    float s = bo[n];
    for (int k = 0; k < Hd; k++) s = fmaf(bv[k], Wo[k*Hd + n], s);
    bvo[n] = s;
}

__global__ void prep_w_kernel(const float* __restrict__ Wr1, __half* __restrict__ W16)
{
    long long idx = (long long)blockIdx.x*blockDim.x + threadIdx.x;
    if (idx >= (long long)Km*Hd*Hd) return;
    int kk = idx & 511;
    int n  = (idx >> 9) & 511;
    int k  = idx >> 18;
    W16[idx] = __float2half_rn(Wr1[((long long)k*Hd + kk)*Hd + n]);
}

// Fused traj+LN, warp-per-row (8 rows/block), two-pass centered stats
__global__ __launch_bounds__(256)
void traj_ln_kernel(const float* __restrict__ coarse,
                    const float* __restrict__ attn,
                    const float* __restrict__ Wt,
                    const float* __restrict__ bt,
                    const float* __restrict__ ln_g,
                    const float* __restrict__ ln_b,
                    __half* __restrict__ XH)
{
    const int wid  = threadIdx.x >> 5;
    const int lane = threadIdx.x & 31;
    const int row  = blockIdx.x * 8 + wid;
    const int k    = row / ROWS_PER_MODE;
    const int rem  = row % ROWS_PER_MODE;
    const int b    = rem / Tt;
    const int t    = rem % Tt;
    const float2 cc = *reinterpret_cast<const float2*>(
        &coarse[((b*Km + k)*Tt + t)*OUTd]);

    float u[16];
    float s = 0.f;
    #pragma unroll
    for (int q=0;q<16;q++){
        int h = q*32 + lane;
        float pre = fmaf(cc.x, Wt[h], fmaf(cc.y, Wt[Hd + h], bt[h]));
        float uu = gelu_exact(pre) + attn[b*Hd + h];
        u[q] = uu;
        s += uu;
    }
    #pragma unroll
    for (int o=16;o>0;o>>=1) s += __shfl_xor_sync(0xffffffffu, s, o);
    const float mean = s * (1.f/512.f);

    float vs = 0.f;
    #pragma unroll
    for (int q=0;q<16;q++){ float d = u[q] - mean; vs = fmaf(d, d, vs); }
    #pragma unroll
    for (int o=16;o>0;o>>=1) vs += __shfl_xor_sync(0xffffffffu, vs, o);
    const float rstd = rsqrtf(vs * (1.f/512.f) + 1e-5f);

    long long rbase = (long long)row * Hd;
    #pragma unroll
    for (int q=0;q<16;q++){
        int h = q*32 + lane;
        float xv = (u[q] - mean) * rstd * ln_g[h] + ln_b[h];
        XH[rbase + h] = __float2half_rn(xv);
    }
}

// ---------------- refine GEMM: fp32-acc HMMA, ldmatrix, 4-stage cp.async --------
// grid (nt=4, mtile=240, mode=6), 256 threads = 8 warps (4 m x 2 n), warp 32x64
__global__ __launch_bounds__(256,2)
void refine_mma_kernel(const __half* __restrict__ XH,
                       const __half* __restrict__ W16,
                       const float* __restrict__ br1,
                       const float* __restrict__ Wr2,
                       float* __restrict__ P)
{
    extern __shared__ char smem[];
    const uint32_t sbase = smem_to_u32(smem);
    const int tid  = threadIdx.x;
    const int wid  = tid >> 5;
    const int lane = tid & 31;
    const int wm   = wid & 3;
    const int wn   = wid >> 2;
    const int nt   = blockIdx.x;
    const int m0   = blockIdx.y * 128;
    const int mode = blockIdx.z;

    const __half* xh = XH  + ((long long)mode * ROWS_PER_MODE + m0) * Hd;
    const __half* wv = W16 + ((long long)mode * Hd + nt * 128) * Hd;

    float acc[2][8][4];
    #pragma unroll
    for (int i=0;i<2;i++)
        #pragma unroll
        for (int j=0;j<8;j++)
            #pragma unroll
            for (int q=0;q<4;q++) acc[i][j][q]=0.f;

    const int lr = tid >> 1;
    const int lh = (tid & 1) * 32;
    auto load_chunk = [&](int c, int stage){
        uint32_t sb = sbase + stage * STAGE;
        const __half* srcs[2] = {xh, wv};
        #pragma unroll
        for (int p = 0; p < 2; p++) {
            uint32_t dst = sb + p*PLANE + lr*ROWB + lh;
            const char* g = (const char*)srcs[p] + ((long long)lr*Hd + c*CH)*2 + lh;
            CP_ASYNC16(dst, g);
            CP_ASYNC16(dst + 16, g + 16);
        }
    };

    load_chunk(0, 0); CP_COMMIT();
    load_chunk(1, 1); CP_COMMIT();
    load_chunk(2, 2); CP_COMMIT();

    const int l16 = lane & 15;
    const int lhf = (lane >> 4) * 16;

    #pragma unroll 1
    for (int c = 0; c < NCHUNK; c++) {
        if (c < NCHUNK-2)       CP_WAITN(2);
        else if (c == NCHUNK-2) CP_WAITN(1);
        else                    CP_WAITN(0);
        __syncthreads();
        if (c + 3 < NCHUNK) { load_chunk(c + 3, (c + 3) & (NSTAGE-1)); CP_COMMIT(); }

        const uint32_t sb = sbase + (c & (NSTAGE-1)) * STAGE;
        #pragma unroll
        for (int ks = 0; ks < 2; ks++) {
            uint32_t ah[2][4];
            #pragma unroll
            for (int i=0;i<2;i++){
                uint32_t a = sb + (wm*32 + i*16 + l16)*ROWB + ks*32 + lhf;
                LDMX4(ah[i][0], ah[i][1], ah[i][2], ah[i][3], a);
            }
            #pragma unroll
            for (int jp=0;jp<4;jp++){
                uint32_t q0,q1,q2,q3;
                uint32_t b = sb + PLANE + (wn*64 + jp*16 + l16)*ROWB + ks*32 + lhf;
                LDMX4(q0,q1,q2,q3, b);
                #pragma unroll
                for (int i=0;i<2;i++){
                    mma16816(acc[i][2*jp+0], ah[i], q0, q2);
                    mma16816(acc[i][2*jp+1], ah[i], q1, q3);
                }
            }
        }
        __syncthreads();
    }

    // epilogue: GELU(pre + br1) dot Wr2
    const float* br1m = br1 + mode * Hd;
    const float* wr2m = Wr2 + mode * Hd * OUTd;
    const int nloc0 = nt*128 + wn*64;

    float p0[2][2], p1[2][2];
    #pragma unroll
    for (int i=0;i<2;i++)
        #pragma unroll
        for (int h2=0;h2<2;h2++){ p0[i][h2]=0.f; p1[i][h2]=0.f; }

    #pragma unroll
    for (int j=0;j<8;j++){
        #pragma unroll
        for (int nn=0;nn<2;nn++){
            const int n = nloc0 + j*8 + (lane&3)*2 + nn;
            const float bv = br1m[n];
            const float w0 = wr2m[n*2+0];
            const float w1 = wr2m[n*2+1];
            #pragma unroll
            for (int i=0;i<2;i++){
                #pragma unroll
                for (int h2=0;h2<2;h2++){
                    float r = gelu_exact(acc[i][j][h2*2+nn] + bv);
                    p0[i][h2] = fmaf(r, w0, p0[i][h2]);
                    p1[i][h2] = fmaf(r, w1, p1[i][h2]);
                }
            }
        }
    }
    #pragma unroll
    for (int i=0;i<2;i++)
        #pragma unroll
        for (int h2=0;h2<2;h2++){
            #pragma unroll
            for (int o=1;o<4;o<<=1){
                p0[i][h2] += __shfl_xor_sync(0xffffffffu, p0[i][h2], o);
                p1[i][h2] += __shfl_xor_sync(0xffffffffu, p1[i][h2], o);
            }
        }

    __syncthreads();
    float* red0 = reinterpret_cast<float*>(smem);
    float* red1 = red0 + 128;
    if (wn == 0 && (lane & 3) == 0){
        #pragma unroll
        for (int i=0;i<2;i++)
            #pragma unroll
            for (int h2=0;h2<2;h2++){
                int rl = wm*32 + i*16 + h2*8 + (lane>>2);
                red0[rl] = p0[i][h2];
                red1[rl] = p1[i][h2];
            }
    }
    __syncthreads();
    if (wn == 1 && (lane & 3) == 0){
        #pragma unroll
        for (int i=0;i<2;i++)
            #pragma unroll
            for (int h2=0;h2<2;h2++){
                int rl = wm*32 + i*16 + h2*8 + (lane>>2);
                long long grow = (long long)mode * ROWS_PER_MODE + m0 + rl;
                long long pidx = ((long long)nt * NROWS + grow) * 2;
                P[pidx + 0] = p0[i][h2] + red0[rl];
                P[pidx + 1] = p1[i][h2] + red1[rl];
            }
    }
}

// predictions = coarse + br2 + sum of 4 ntile partials
__global__ void finalize_kernel(const float* __restrict__ coarse,
                                const float* __restrict__ br2,
                                const float* __restrict__ P,
                                float* __restrict__ out)
{
    int idx = blockIdx.x*blockDim.x + threadIdx.x;
    if (idx >= PRED_ELEMS) return;
    int o = idx & 1;
    int t = (idx >> 1) % Tt;
    int k = ((idx >> 1) / Tt) % Km;
    int b = idx / (2*Tt*Km);
    long long grow = (long long)k * ROWS_PER_MODE + b * Tt + t;
    float s = coarse[idx] + br2[k*2+o];
    #pragma unroll
    for (int nt=0; nt<4; nt++)
        s += P[((long long)nt * NROWS + grow)*2 + o];
    out[idx] = s;
}

// conf head epilogue + softmax (c1 holds raw pre-activation; ReLU applied here)
__global__ __launch_bounds__(192)
void conf_softmax_kernel(const float* __restrict__ C1,
                         const float* __restrict__ Wf2,
                         const float* __restrict__ bf2,
                         float* __restrict__ out)
{
    int b = blockIdx.x;
    int tid = threadIdx.x;
    int k = tid >> 5, lane = tid & 31;
    __shared__ float cf[Km];
    const float* row = C1 + (b*Km + k)*64;
    float s = fmaxf(row[lane],      0.f) * Wf2[lane]
            + fmaxf(row[32 + lane], 0.f) * Wf2[32 + lane];
    #pragma unroll
    for (int o=16;o>0;o>>=1) s += __shfl_xor_sync(0xffffffffu, s, o);
    if (lane == 0) cf[k] = s + bf2[0];
    __syncthreads();
    if (tid < Km){
        float m = cf[0];
        #pragma unroll
        for (int i=1;i<Km;i++) m = fmaxf(m, cf[i]);
        float denom = 0.f;
        #pragma unroll
        for (int i=0;i<Km;i++) denom += expf(cf[i]-m);
        out[PRED_ELEMS + b*Km + tid] = expf(cf[tid]-m)/denom;
    }
}

// ------------------------------- launch ------------------------------------------
extern "C" void kernel_launch(void* const* d_in, const int* in_sizes, int n_in,
                              void* d_out, int out_size)
{
    const float* interaction = (const float*)d_in[0];
    const float* cooperative = (const float*)d_in[1];
    const float* map_ctx     = (const float*)d_in[2];
    const float* mode_q      = (const float*)d_in[3];
    const float* Wc1 = (const float*)d_in[4];
    const float* bc1 = (const float*)d_in[5];
    const float* Wc2 = (const float*)d_in[6];
    const float* bc2 = (const float*)d_in[7];
    const float* Wk1 = (const float*)d_in[8];
    const float* bk1 = (const float*)d_in[9];
    const float* Wk2 = (const float*)d_in[10];
    const float* bk2 = (const float*)d_in[11];
    const float* Wt  = (const float*)d_in[12];
    const float* bt  = (const float*)d_in[13];
    const float* Wv  = (const float*)d_in[18];
    const float* bv  = (const float*)d_in[19];
    const float* Wo  = (const float*)d_in[20];
    const float* bo  = (const float*)d_in[21];
    const float* lng = (const float*)d_in[22];
    const float* lnb = (const float*)d_in[23];
    const float* Wr1 = (const float*)d_in[24];
    const float* br1 = (const float*)d_in[25];
    const float* Wr2 = (const float*)d_in[26];
    const float* br2 = (const float*)d_in[27];
    const float* Wf1 = (const float*)d_in[28];
    const float* bf1 = (const float*)d_in[29];
    const float* Wf2 = (const float*)d_in[30];
    const float* bf2 = (const float*)d_in[31];
    float* out = (float*)d_out;

    float *accbuf, *hbuf, *part, *bvo, *zero;
    __half *xh, *w16;
    cudaGetSymbolAddress((void**)&accbuf, g_accbuf);
    cudaGetSymbolAddress((void**)&hbuf,   g_h);
    cudaGetSymbolAddress((void**)&part,   g_part);
    cudaGetSymbolAddress((void**)&bvo,    g_bvo);
    cudaGetSymbolAddress((void**)&zero,   g_zero512);
    cudaGetSymbolAddress((void**)&xh,     g_xh);
    cudaGetSymbolAddress((void**)&w16,    g_w16);

    float* wvo    = accbuf + OFF_WVO;
    float* tmp1   = accbuf + OFF_TMP1;
    float* ctx    = accbuf + OFF_CTX;
    float* attn   = accbuf + OFF_ATTN;
    float* coarse = accbuf + OFF_COARSE;
    float* c1     = accbuf + OFF_C1;

    static cudaStream_t s1 = nullptr, s2 = nullptr;
    static cudaEvent_t evRoot, evCtx, evAttn, evPrep, evConf;
    if (!s1) {
        cudaStreamCreateWithFlags(&s1, cudaStreamNonBlocking);
        cudaStreamCreateWithFlags(&s2, cudaStreamNonBlocking);
        cudaEventCreateWithFlags(&evRoot, cudaEventDisableTiming);
        cudaEventCreateWithFlags(&evCtx,  cudaEventDisableTiming);
        cudaEventCreateWithFlags(&evAttn, cudaEventDisableTiming);
        cudaEventCreateWithFlags(&evPrep, cudaEventDisableTiming);
        cudaEventCreateWithFlags(&evConf, cudaEventDisableTiming);
        cudaFuncSetAttribute(refine_mma_kernel,
                             cudaFuncAttributeMaxDynamicSharedMemorySize, SMEM_DYN);
    }

    // ---- fork ----
    cudaEventRecord(evRoot, 0);
    cudaStreamWaitEvent(s1, evRoot, 0);
    cudaStreamWaitEvent(s2, evRoot, 0);

    // s1: refine weight prep (independent)
    prep_w_kernel<<<(Km*Hd*Hd + 255)/256, 256, 0, s1>>>(Wr1, w16);
    cudaEventRecord(evPrep, s1);

    // s2: wvo = Wv@Wo (+ its memset) and bvo (independent of data chain)
    cudaMemsetAsync(wvo, 0, (size_t)Hd*Hd*sizeof(float), s2);
    sgemmskb<AM_PLAIN><<<dim3(8,8,8),256,0,s2>>>(Wv,nullptr,nullptr,0,Hd, Wo,0,Hd, zero,0,
                                                 wvo,0,Hd, Hd,Hd, Hd/8, 8);
    bvo_kernel<<<2,256,0,s2>>>(bv, Wo, bo, bvo);

    // s0: main chain — memset rest of accumulators, then context_proj
    cudaMemsetAsync(tmp1, 0, (size_t)(ACC_TOTAL - OFF_TMP1)*sizeof(float));
    sgemmskb<AM_CONCAT><<<dim3(8,8,8),256>>>(interaction,cooperative,map_ctx,0,0,
                                             Wc1,0,Hd, bc1,0, tmp1,0,Hd, Bsz,Hd, (3*Hd)/8, 8);
    sgemmskb<AM_GELU><<<dim3(8,8,8),256>>>(tmp1,nullptr,nullptr,0,Hd,
                                           Wc2,0,Hd, bc2,0, ctx,0,Hd, Bsz,Hd, Hd/8, 8);
    cudaEventRecord(evCtx, 0);

    // s2: attn = ctx @ wvo + bvo (needs ctx + wvo)
    cudaStreamWaitEvent(s2, evCtx, 0);
    sgemmskb<AM_PLAIN><<<dim3(8,8,8),256,0,s2>>>(ctx,nullptr,nullptr,0,Hd,
                                                 wvo,0,Hd, bvo,0, attn,0,Hd, Bsz,Hd, Hd/8, 8);
    cudaEventRecord(evAttn, s2);

    // s1: confidence branch (needs ctx; joins only at graph end via evConf)
    cudaStreamWaitEvent(s1, evCtx, 0);
    sgemmskb<AM_CONF><<<dim3(1,48,4),256,0,s1>>>(ctx,mode_q,nullptr,0,0,
                                                 Wf1,0,64, bf1,0, c1,0,64, Bsz*Km,64, Hd/4, 4);
    conf_softmax_kernel<<<Bsz,192,0,s1>>>(c1, Wf2, bf2, out);
    cudaEventRecord(evConf, s1);

    // s0: coarse heads
    sgemm64<ACT_NONE,AM_CTXQ><<<dim3(16,8,Km),256>>>(ctx,mode_q,nullptr,0,0,
                                                     Wk1,(long long)Hd*H2,H2,
                                                     bk1,H2, hbuf,H2,Km*H2, Bsz,H2,Hd);
    sgemmskb<AM_GELU><<<dim3(2,8,Km*4),256>>>(hbuf,nullptr,nullptr,H2,Km*H2,
                                              Wk2,(long long)H2*TO,TO,
                                              bk2,TO, coarse,TO,Km*TO, Bsz,TO, H2/4, 4);

    // s0: traj+LN (needs coarse on s0 + attn from s2)
    cudaStreamWaitEvent(0, evAttn, 0);
    traj_ln_kernel<<<NROWS/8,256>>>(coarse, attn, Wt, bt, lng, lnb, xh);

    // s0: refine GEMM (needs xh + w16 from s1's prep)
    cudaStreamWaitEvent(0, evPrep, 0);
    refine_mma_kernel<<<dim3(4,240,Km),256, SMEM_DYN>>>(xh, w16, br1, Wr2, part);

    // s0: predictions; join conf branch
    finalize_kernel<<<(PRED_ELEMS + 255)/256, 256>>>(coarse, br2, part, out);
    cudaStreamWaitEvent(0, evConf, 0);
}